// round 1
// baseline (speedup 1.0000x reference)
#include <cuda_runtime.h>
#include <cuda_bf16.h>

// Problem constants (PairInitOPM: B=1, L=768, sd=384, pd=128)
#define Lq 768
#define SD 384
#define PD 128

// Scratch (allocation-free rule: __device__ globals)
__device__ float g_P[Lq * PD];  // si  (includes bi)
__device__ float g_Q[Lq * PD];  // sj  (includes bj)
__device__ float g_U[Lq * PD];  // zi + bm
__device__ float g_V[Lq * PD];  // zj

// ---------------------------------------------------------------------------
// Kernel 1: per block, TI rows of s.
//   Phase A: [TI,384] @ [384,256]^T -> si|sj  (cols 0..127 = si, 128..255 = sj)
//   Phase B: zi[e] = sum_d si[d]*wm[e][d], zj[e] = sum_d sj[d]*wm[e][128+d]
// ---------------------------------------------------------------------------
#define TI 4
#define KT 32

__global__ __launch_bounds__(256) void k1_proj(
    const float* __restrict__ s,
    const float* __restrict__ wi, const float* __restrict__ bi,
    const float* __restrict__ wj, const float* __restrict__ bj,
    const float* __restrict__ wm, const float* __restrict__ bm)
{
    __shared__ float s_sh[TI][SD];           // 6 KB
    __shared__ float w_sh[256][KT + 1];      // 33.8 KB (padded: conflict-free)
    __shared__ float sisj[TI][2 * PD];       // 4 KB

    const int t  = threadIdx.x;              // 0..255  (output column c)
    const int i0 = blockIdx.x * TI;

    // Load s rows for this block (coalesced)
    for (int idx = t; idx < TI * SD; idx += 256) {
        int r = idx / SD, k = idx - r * SD;
        s_sh[r][k] = s[(i0 + r) * SD + k];
    }

    float acc[TI];
#pragma unroll
    for (int r = 0; r < TI; r++) acc[r] = 0.f;

    // ---- Phase A: si/sj GEMM with k-tiled, coalesced weight staging ----
    for (int k0 = 0; k0 < SD; k0 += KT) {
        __syncthreads();
        // Stage weight tile: w_sh[c][kk] = W[c][k0+kk], W = rows of wi then wj.
        // Each warp-instr reads 32 contiguous floats of one weight row.
        for (int idx = t; idx < 256 * KT; idx += 256) {
            int c  = idx >> 5;
            int kk = idx & 31;
            const float* wr = (c < PD) ? (wi + c * SD) : (wj + (c - PD) * SD);
            w_sh[c][kk] = wr[k0 + kk];
        }
        __syncthreads();
#pragma unroll
        for (int kk = 0; kk < KT; kk++) {
            float w = w_sh[t][kk];            // banks (t+kk)%32 — conflict-free
#pragma unroll
            for (int r = 0; r < TI; r++)
                acc[r] = fmaf(s_sh[r][k0 + kk], w, acc[r]);  // s_sh: broadcast
        }
    }

    {
        float b = (t < PD) ? bi[t] : bj[t - PD];
#pragma unroll
        for (int r = 0; r < TI; r++) acc[r] += b;
    }

    __syncthreads();
#pragma unroll
    for (int r = 0; r < TI; r++) sisj[r][t] = acc[r];

    // ---- Phase B: zi/zj. Thread t: which = t>>7, e = t&127. ----
    const int which = t >> 7;
    const int e     = t & 127;
    float accz[TI];
#pragma unroll
    for (int r = 0; r < TI; r++) accz[r] = 0.f;

    for (int k0 = 0; k0 < PD; k0 += KT) {
        __syncthreads();
        // Stage wmx tile: wmx[c][k] = wm[(c&127)*256 + (c>>7)*128 + k]
        for (int idx = t; idx < 256 * KT; idx += 256) {
            int c  = idx >> 5;
            int kk = idx & 31;
            w_sh[c][kk] = wm[(c & 127) * (2 * PD) + (c >> 7) * PD + k0 + kk];
        }
        __syncthreads();
#pragma unroll
        for (int kk = 0; kk < KT; kk++) {
            float w = w_sh[t][kk];
#pragma unroll
            for (int r = 0; r < TI; r++)
                accz[r] = fmaf(sisj[r][which * PD + k0 + kk], w, accz[r]);
        }
    }

    const float bmv = bm[e];
#pragma unroll
    for (int r = 0; r < TI; r++) {
        int i = i0 + r;
        if (which == 0) {
            g_P[i * PD + e] = acc[r];
            g_U[i * PD + e] = accz[r] + bmv;
        } else {
            g_Q[i * PD + e] = acc[r];
            g_V[i * PD + e] = accz[r];
        }
    }
}

// ---------------------------------------------------------------------------
// Kernel 2: z0[i,j,d] = U[i,d] + V[j,d] + P[i,d]*Q[j,d]
// Block = (32 d-quads, 8 i). Each block: 8 i x 64 j tile. Streaming stores.
// ---------------------------------------------------------------------------
#define BJ 64

__global__ __launch_bounds__(256) void k2_outer(float* __restrict__ out)
{
    const int tx = threadIdx.x & 31;    // d quad: d = 4*tx
    const int ty = threadIdx.x >> 5;    // i within tile (0..7)
    const int i  = blockIdx.x * 8 + ty;
    const int j0 = blockIdx.y * BJ;

    const float4* __restrict__ P4 = (const float4*)g_P;
    const float4* __restrict__ Q4 = (const float4*)g_Q;
    const float4* __restrict__ U4 = (const float4*)g_U;
    const float4* __restrict__ V4 = (const float4*)g_V;

    const float4 p = P4[i * 32 + tx];
    const float4 u = U4[i * 32 + tx];

    float4* out4 = (float4*)out;
    size_t base = ((size_t)i * Lq + j0) * 32 + tx;

#pragma unroll 4
    for (int jj = 0; jj < BJ; jj++) {
        float4 q = Q4[(j0 + jj) * 32 + tx];   // L1/L2 hit (1.6 MB read set)
        float4 v = V4[(j0 + jj) * 32 + tx];
        float4 o;
        o.x = fmaf(p.x, q.x, u.x + v.x);
        o.y = fmaf(p.y, q.y, u.y + v.y);
        o.z = fmaf(p.z, q.z, u.z + v.z);
        o.w = fmaf(p.w, q.w, u.w + v.w);
        __stcs(&out4[base + (size_t)jj * 32], o);  // streaming: don't pollute L2
    }
}

// ---------------------------------------------------------------------------
extern "C" void kernel_launch(void* const* d_in, const int* in_sizes, int n_in,
                              void* d_out, int out_size)
{
    const float* s  = (const float*)d_in[0];
    const float* wi = (const float*)d_in[1];
    const float* bi = (const float*)d_in[2];
    const float* wj = (const float*)d_in[3];
    const float* bj = (const float*)d_in[4];
    const float* wm = (const float*)d_in[5];
    const float* bm = (const float*)d_in[6];
    float* out = (float*)d_out;

    k1_proj<<<Lq / TI, 256>>>(s, wi, bi, wj, bj, wm, bm);

    dim3 grid2(Lq / 8, Lq / BJ);
    k2_outer<<<grid2, 256>>>(out);
}

// round 2
// speedup vs baseline: 1.2580x; 1.2580x over previous
#include <cuda_runtime.h>
#include <cuda_bf16.h>

// Problem constants (PairInitOPM: B=1, L=768, sd=384, pd=128)
#define Lq 768
#define SD 384
#define PD 128

// Scratch (allocation-free rule: __device__ globals)
__device__ float g_P[Lq * PD];  // si  (includes bi)
__device__ float g_Q[Lq * PD];  // sj  (includes bj)
__device__ float g_U[Lq * PD];  // zi + bm
__device__ float g_V[Lq * PD];  // zj

// ---------------------------------------------------------------------------
// Kernel 1: per block, TI rows of s. Double-buffered weight tiles so the
// L2 weight fetch overlaps the FMA loop (one __syncthreads per tile).
//   Phase A: [TI,384] @ [384,256]^T -> si|sj (cols 0..127 = si, 128..255 = sj)
//   Phase B: zi[e] = sum_d si[d]*wm[e][d], zj[e] = sum_d sj[d]*wm[e][128+d]
// ---------------------------------------------------------------------------
#define TI 4
#define KT 16
#define NTA (SD / KT)   // 24 tiles, phase A
#define NTB (PD / KT)   // 8 tiles, phase B

__global__ __launch_bounds__(256) void k1_proj(
    const float* __restrict__ s,
    const float* __restrict__ wi, const float* __restrict__ bi,
    const float* __restrict__ wj, const float* __restrict__ bj,
    const float* __restrict__ wm, const float* __restrict__ bm)
{
    __shared__ float s_sh[TI][SD];            // 6 KB
    __shared__ float w_sh[2][256][KT + 1];    // 34 KB (padded, double buffer)
    __shared__ float sisj[TI][2 * PD];        // 4 KB   -> 44 KB total (<48 KB)

    const int t  = threadIdx.x;               // 0..255 (output column c)
    const int i0 = blockIdx.x * TI;

    for (int idx = t; idx < TI * SD; idx += 256) {
        int r = idx / SD, k = idx - r * SD;
        s_sh[r][k] = s[(i0 + r) * SD + k];
    }

    float acc[TI];
#pragma unroll
    for (int r = 0; r < TI; r++) acc[r] = 0.f;

    // ---- Phase A ----
    // stage tile 0 into buffer 0 (16 elems/thread: idx = t + m*256)
#pragma unroll
    for (int m = 0; m < KT; m++) {
        int idx = t + m * 256;
        int c = idx >> 4, kk = idx & 15;
        const float* wr = (c < PD) ? (wi + c * SD) : (wj + (c - PD) * SD);
        w_sh[0][c][kk] = wr[kk];
    }
    __syncthreads();   // covers s_sh too

    for (int tile = 0; tile < NTA; tile++) {
        if (tile + 1 < NTA) {     // prefetch next tile into the other buffer
            const int k0n = (tile + 1) * KT, bn = (tile + 1) & 1;
#pragma unroll
            for (int m = 0; m < KT; m++) {
                int idx = t + m * 256;
                int c = idx >> 4, kk = idx & 15;
                const float* wr = (c < PD) ? (wi + c * SD) : (wj + (c - PD) * SD);
                w_sh[bn][c][kk] = wr[k0n + kk];
            }
        }
        const int b = tile & 1, k0 = tile * KT;
#pragma unroll
        for (int kk = 0; kk < KT; kk++) {
            float w = w_sh[b][t][kk];          // pad 17: conflict-free
#pragma unroll
            for (int r = 0; r < TI; r++)
                acc[r] = fmaf(s_sh[r][k0 + kk], w, acc[r]);
        }
        __syncthreads();
    }

    {
        float bbb = (t < PD) ? bi[t] : bj[t - PD];
#pragma unroll
        for (int r = 0; r < TI; r++) acc[r] += bbb;
    }

#pragma unroll
    for (int r = 0; r < TI; r++) sisj[r][t] = acc[r];

    // ---- Phase B ----
    const int which = t >> 7;     // 0 -> zi path, 1 -> zj path
    const int e     = t & 127;
    float accz[TI];
#pragma unroll
    for (int r = 0; r < TI; r++) accz[r] = 0.f;

    // stage tile 0 (buffer 0); sync also publishes sisj
#pragma unroll
    for (int m = 0; m < KT; m++) {
        int idx = t + m * 256;
        int c = idx >> 4, kk = idx & 15;
        w_sh[0][c][kk] = wm[(c & 127) * (2 * PD) + (c >> 7) * PD + kk];
    }
    __syncthreads();

    for (int tile = 0; tile < NTB; tile++) {
        if (tile + 1 < NTB) {
            const int k0n = (tile + 1) * KT, bn = (tile + 1) & 1;
#pragma unroll
            for (int m = 0; m < KT; m++) {
                int idx = t + m * 256;
                int c = idx >> 4, kk = idx & 15;
                w_sh[bn][c][kk] = wm[(c & 127) * (2 * PD) + (c >> 7) * PD + k0n + kk];
            }
        }
        const int b = tile & 1, k0 = tile * KT;
#pragma unroll
        for (int kk = 0; kk < KT; kk++) {
            float w = w_sh[b][t][kk];
#pragma unroll
            for (int r = 0; r < TI; r++)
                accz[r] = fmaf(sisj[r][which * PD + k0 + kk], w, accz[r]);
        }
        __syncthreads();
    }

    const float bmv = bm[e];
#pragma unroll
    for (int r = 0; r < TI; r++) {
        int i = i0 + r;
        if (which == 0) {
            g_P[i * PD + e] = acc[r];
            g_U[i * PD + e] = accz[r] + bmv;
        } else {
            g_Q[i * PD + e] = acc[r];
            g_V[i * PD + e] = accz[r];
        }
    }
}

// ---------------------------------------------------------------------------
// Kernel 2: z0[i,j,d] = U[i,d] + V[j,d] + P[i,d]*Q[j,d]
// Block = 8 i x 32 j tile. Q/V j-tile staged in smem (32 KB) so the store
// loop has NO global-load dependency (kills long_scoreboard stalls).
// Streaming float4 stores.
// ---------------------------------------------------------------------------
#define BI 8
#define BJ 32

__global__ __launch_bounds__(256) void k2_outer(float* __restrict__ out)
{
    __shared__ float4 q_sh[BJ * 32];   // 16 KB
    __shared__ float4 v_sh[BJ * 32];   // 16 KB

    const int t  = threadIdx.x;
    const int tx = t & 31;             // d quad: d = 4*tx
    const int ty = t >> 5;             // i within tile (0..7)
    const int i  = blockIdx.x * BI + ty;
    const int j0 = blockIdx.y * BJ;

    const float4* __restrict__ P4 = (const float4*)g_P;
    const float4* __restrict__ Q4 = (const float4*)g_Q;
    const float4* __restrict__ U4 = (const float4*)g_U;
    const float4* __restrict__ V4 = (const float4*)g_V;

    // Cooperative stage of the j-tile (4 float4 per thread per array; L2 hits)
#pragma unroll
    for (int m = 0; m < (BJ * 32) / 256; m++) {
        int idx = t + m * 256;
        q_sh[idx] = Q4[j0 * 32 + idx];
        v_sh[idx] = V4[j0 * 32 + idx];
    }

    const float4 p = P4[i * 32 + tx];
    const float4 u = U4[i * 32 + tx];
    __syncthreads();

    float4* out4 = (float4*)out;
    size_t base = ((size_t)i * Lq + j0) * 32 + tx;

#pragma unroll 8
    for (int jj = 0; jj < BJ; jj++) {
        float4 q = q_sh[jj * 32 + tx];     // LDS.128, conflict-free
        float4 v = v_sh[jj * 32 + tx];
        float4 o;
        o.x = fmaf(p.x, q.x, u.x + v.x);
        o.y = fmaf(p.y, q.y, u.y + v.y);
        o.z = fmaf(p.z, q.z, u.z + v.z);
        o.w = fmaf(p.w, q.w, u.w + v.w);
        __stcs(&out4[base + (size_t)jj * 32], o);  // streaming store
    }
}

// ---------------------------------------------------------------------------
extern "C" void kernel_launch(void* const* d_in, const int* in_sizes, int n_in,
                              void* d_out, int out_size)
{
    const float* s  = (const float*)d_in[0];
    const float* wi = (const float*)d_in[1];
    const float* bi = (const float*)d_in[2];
    const float* wj = (const float*)d_in[3];
    const float* bj = (const float*)d_in[4];
    const float* wm = (const float*)d_in[5];
    const float* bm = (const float*)d_in[6];
    float* out = (float*)d_out;

    k1_proj<<<Lq / TI, 256>>>(s, wi, bi, wj, bj, wm, bm);

    dim3 grid2(Lq / BI, Lq / BJ);
    k2_outer<<<grid2, 256>>>(out);
}

// round 3
// speedup vs baseline: 1.5574x; 1.2379x over previous
#include <cuda_runtime.h>
#include <cuda_bf16.h>

// Problem constants (PairInitOPM: B=1, L=768, sd=384, pd=128)
#define Lq 768
#define SD 384
#define PD 128

// Scratch (allocation-free rule: __device__ globals)
__device__ float g_P[Lq * PD];  // si  (includes bi)
__device__ float g_Q[Lq * PD];  // sj  (includes bj)
__device__ float g_U[Lq * PD];  // zi + bm
__device__ float g_V[Lq * PD];  // zj

// ---------------------------------------------------------------------------
// Kernel 1: TI=6 rows/block -> 128 blocks = ONE wave on 148 SMs.
// Single-buffer k-tiles, coalesced warp-row staging (no register prefetch).
//   Phase A: [TI,384] @ [384,256]^T -> si|sj (cols 0..127 = si, 128..255 = sj)
//   Phase B: zi[e] = sum_d si[d]*wm[e][d], zj[e] = sum_d sj[d]*wm[e][128+d]
// ---------------------------------------------------------------------------
#define TI 6
#define KT 32
#define NTA (SD / KT)   // 12 tiles, phase A
#define NTB (PD / KT)   // 4 tiles, phase B

__global__ __launch_bounds__(256) void k1_proj(
    const float* __restrict__ s,
    const float* __restrict__ wi, const float* __restrict__ bi,
    const float* __restrict__ wj, const float* __restrict__ bj,
    const float* __restrict__ wm, const float* __restrict__ bm)
{
    __shared__ float w_sh[256][KT + 1];   // 33.8 KB, pad 33: conflict-free
    __shared__ float s_sh[TI][SD];        // 9.2 KB (overlaid by sisj in phase B)

    const int t    = threadIdx.x;         // 0..255 (output column c)
    const int i0   = blockIdx.x * TI;
    const int cw   = t >> 5;              // warp id: staging base column
    const int lane = t & 31;

    // Load s rows for this block (coalesced)
    for (int idx = t; idx < TI * SD; idx += 256) {
        int r = idx / SD, k = idx - r * SD;
        s_sh[r][k] = s[(i0 + r) * SD + k];
    }

    float acc[TI];
#pragma unroll
    for (int r = 0; r < TI; r++) acc[r] = 0.f;

    // ---- Phase A ----
    for (int tile = 0; tile < NTA; tile++) {
        const int k0 = tile * KT;
        __syncthreads();                  // w_sh free (also covers s_sh on tile 0)
        // Warp w stages columns {w, w+8, ..., w+248}; each warp-instr reads
        // 128 contiguous bytes of one weight row. 32 independent LDG/thread.
#pragma unroll
        for (int m = 0; m < 32; m++) {
            int c = cw + 8 * m;
            const float* wr = (c < PD) ? (wi + c * SD) : (wj + (c - PD) * SD);
            w_sh[c][lane] = wr[k0 + lane];
        }
        __syncthreads();
#pragma unroll
        for (int kk = 0; kk < KT; kk++) {
            float w = w_sh[t][kk];        // (33t+kk)%32 = (t+kk)%32: conflict-free
#pragma unroll
            for (int r = 0; r < TI; r++)
                acc[r] = fmaf(s_sh[r][k0 + kk], w, acc[r]);   // broadcast
        }
    }

    {
        float b = (t < PD) ? bi[t] : bj[t - PD];
#pragma unroll
        for (int r = 0; r < TI; r++) acc[r] += b;
    }

    // ---- Publish sisj, overlaying the dead s_sh region ----
    float* sisj = &s_sh[0][0];            // TI*256 floats <= TI*384
    __syncthreads();                      // everyone done reading s_sh
#pragma unroll
    for (int r = 0; r < TI; r++) sisj[r * 256 + t] = acc[r];

    // ---- Phase B ----
    const int which = t >> 7;             // 0 -> zi path, 1 -> zj path
    const int e     = t & 127;
    float accz[TI];
#pragma unroll
    for (int r = 0; r < TI; r++) accz[r] = 0.f;

    for (int tile = 0; tile < NTB; tile++) {
        const int k0 = tile * KT;
        __syncthreads();                  // w_sh free (also publishes sisj on tile 0)
#pragma unroll
        for (int m = 0; m < 32; m++) {
            int c = cw + 8 * m;
            w_sh[c][lane] = wm[(c & 127) * (2 * PD) + (c >> 7) * PD + k0 + lane];
        }
        __syncthreads();
#pragma unroll
        for (int kk = 0; kk < KT; kk++) {
            float w = w_sh[t][kk];
#pragma unroll
            for (int r = 0; r < TI; r++)
                accz[r] = fmaf(sisj[r * 256 + which * PD + k0 + kk], w, accz[r]);
        }
    }

    const float bmv = bm[e];
#pragma unroll
    for (int r = 0; r < TI; r++) {
        int i = i0 + r;
        if (which == 0) {
            g_P[i * PD + e] = acc[r];
            g_U[i * PD + e] = accz[r] + bmv;
        } else {
            g_Q[i * PD + e] = acc[r];
            g_V[i * PD + e] = accz[r];
        }
    }
}

// ---------------------------------------------------------------------------
// Kernel 2: z0[i,j,d] = U[i,d] + V[j,d] + P[i,d]*Q[j,d]
// Block = 8 i x 32 j tile. Q/V j-tile staged in smem; streaming float4 stores.
// (Measured at ~48us, ~90% of practical DRAM floor — unchanged.)
// ---------------------------------------------------------------------------
#define BI 8
#define BJ 32

__global__ __launch_bounds__(256) void k2_outer(float* __restrict__ out)
{
    __shared__ float4 q_sh[BJ * 32];   // 16 KB
    __shared__ float4 v_sh[BJ * 32];   // 16 KB

    const int t  = threadIdx.x;
    const int tx = t & 31;             // d quad: d = 4*tx
    const int ty = t >> 5;             // i within tile (0..7)
    const int i  = blockIdx.x * BI + ty;
    const int j0 = blockIdx.y * BJ;

    const float4* __restrict__ P4 = (const float4*)g_P;
    const float4* __restrict__ Q4 = (const float4*)g_Q;
    const float4* __restrict__ U4 = (const float4*)g_U;
    const float4* __restrict__ V4 = (const float4*)g_V;

#pragma unroll
    for (int m = 0; m < (BJ * 32) / 256; m++) {
        int idx = t + m * 256;
        q_sh[idx] = Q4[j0 * 32 + idx];
        v_sh[idx] = V4[j0 * 32 + idx];
    }

    const float4 p = P4[i * 32 + tx];
    const float4 u = U4[i * 32 + tx];
    __syncthreads();

    float4* out4 = (float4*)out;
    size_t base = ((size_t)i * Lq + j0) * 32 + tx;

#pragma unroll 8
    for (int jj = 0; jj < BJ; jj++) {
        float4 q = q_sh[jj * 32 + tx];     // LDS.128, conflict-free
        float4 v = v_sh[jj * 32 + tx];
        float4 o;
        o.x = fmaf(p.x, q.x, u.x + v.x);
        o.y = fmaf(p.y, q.y, u.y + v.y);
        o.z = fmaf(p.z, q.z, u.z + v.z);
        o.w = fmaf(p.w, q.w, u.w + v.w);
        __stcs(&out4[base + (size_t)jj * 32], o);  // streaming store
    }
}

// ---------------------------------------------------------------------------
extern "C" void kernel_launch(void* const* d_in, const int* in_sizes, int n_in,
                              void* d_out, int out_size)
{
    const float* s  = (const float*)d_in[0];
    const float* wi = (const float*)d_in[1];
    const float* bi = (const float*)d_in[2];
    const float* wj = (const float*)d_in[3];
    const float* bj = (const float*)d_in[4];
    const float* wm = (const float*)d_in[5];
    const float* bm = (const float*)d_in[6];
    float* out = (float*)d_out;

    k1_proj<<<Lq / TI, 256>>>(s, wi, bi, wj, bj, wm, bm);

    dim3 grid2(Lq / BI, Lq / BJ);
    k2_outer<<<grid2, 256>>>(out);
}

// round 4
// speedup vs baseline: 1.5632x; 1.0038x over previous
#include <cuda_runtime.h>
#include <cuda_bf16.h>
#include <cstdint>

// Problem constants (PairInitOPM: B=1, L=768, sd=384, pd=128)
#define Lq 768
#define SD 384
#define PD 128

// Scratch (allocation-free rule: __device__ globals)
__device__ float g_P[Lq * PD];  // si  (includes bi)
__device__ float g_Q[Lq * PD];  // sj  (includes bj)
__device__ float g_U[Lq * PD];  // zi + bm
__device__ float g_V[Lq * PD];  // zj

// ---------------------------------------------------------------------------
// Kernel 1: TI=6 rows/block -> 128 blocks = ONE wave.
// cp.async double-buffered weight tiles: stage(t+1) overlaps compute(t).
// Dynamic smem layout: w_sh[2][256][33] then s_sh[6*384] (76.8 KB).
// ---------------------------------------------------------------------------
#define TI 6
#define KT 32
#define NTA (SD / KT)   // 12
#define NTB (PD / KT)   // 4
#define WROW 33         // padded row: (33t+kk)%32=(t+kk)%32 -> conflict-free
#define WBUF (256 * WROW)
#define K1_SMEM_BYTES ((2 * WBUF + TI * SD) * 4)

__device__ __forceinline__ void cp_async4(uint32_t dst_smem, const void* src) {
    asm volatile("cp.async.ca.shared.global [%0], [%1], 4;" :: "r"(dst_smem), "l"(src));
}
__device__ __forceinline__ void cp_commit() {
    asm volatile("cp.async.commit_group;");
}
template <int N>
__device__ __forceinline__ void cp_wait() {
    asm volatile("cp.async.wait_group %0;" :: "n"(N));
}

__global__ __launch_bounds__(256) void k1_proj(
    const float* __restrict__ s,
    const float* __restrict__ wi, const float* __restrict__ bi,
    const float* __restrict__ wj, const float* __restrict__ bj,
    const float* __restrict__ wm, const float* __restrict__ bm)
{
    extern __shared__ float smem[];
    float* w_sh = smem;                 // [2][256][WROW]
    float* s_sh = smem + 2 * WBUF;      // [TI][SD]; overlaid by sisj in phase B

    const int t    = threadIdx.x;       // 0..255 (output column c)
    const int i0   = blockIdx.x * TI;
    const int cw   = t >> 5;            // warp id: staging base column
    const int lane = t & 31;

    const uint32_t w_sh_sm = (uint32_t)__cvta_generic_to_shared(w_sh);

    // Load s rows (regular loads; covered by first barrier)
    for (int idx = t; idx < TI * SD; idx += 256) {
        int r = idx / SD, k = idx - r * SD;
        s_sh[r * SD + k] = s[(i0 + r) * SD + k];
    }

    float acc[TI];
#pragma unroll
    for (int r = 0; r < TI; r++) acc[r] = 0.f;

    // ---------------- Phase A ----------------
    // stage(tile, buf): thread handles rows c = cw + 8m, element [k0+lane]
    auto stageA = [&](int tile, int b) {
        const int k0 = tile * KT;
#pragma unroll
        for (int m = 0; m < 32; m++) {
            int c = cw + 8 * m;
            const float* wr = (c < PD) ? (wi + c * SD) : (wj + (c - PD) * SD);
            cp_async4(w_sh_sm + (uint32_t)((b * WBUF + c * WROW + lane) * 4),
                      wr + k0 + lane);
        }
        cp_commit();
    };

    stageA(0, 0);
    for (int tile = 0; tile < NTA; tile++) {
        if (tile + 1 < NTA) { stageA(tile + 1, (tile + 1) & 1); cp_wait<1>(); }
        else                { cp_wait<0>(); }
        __syncthreads();                              // tile `tile` visible to all
        const float* wb = w_sh + (tile & 1) * WBUF;
        const int k0 = tile * KT;
#pragma unroll
        for (int kk = 0; kk < KT; kk++) {
            float w = wb[t * WROW + kk];
#pragma unroll
            for (int r = 0; r < TI; r++)
                acc[r] = fmaf(s_sh[r * SD + k0 + kk], w, acc[r]);  // broadcast
        }
        __syncthreads();                              // buffer reusable
    }

    {
        float b = (t < PD) ? bi[t] : bj[t - PD];
#pragma unroll
        for (int r = 0; r < TI; r++) acc[r] += b;
    }

    // Publish sisj into the dead s_sh region (last phase-A barrier passed)
    float* sisj = s_sh;                 // [TI][256]
#pragma unroll
    for (int r = 0; r < TI; r++) sisj[r * 256 + t] = acc[r];

    // ---------------- Phase B ----------------
    const int which = t >> 7;           // 0 -> zi, 1 -> zj
    const int e     = t & 127;
    float accz[TI];
#pragma unroll
    for (int r = 0; r < TI; r++) accz[r] = 0.f;

    auto stageB = [&](int tile, int b) {
        const int k0 = tile * KT;
#pragma unroll
        for (int m = 0; m < 32; m++) {
            int c = cw + 8 * m;
            cp_async4(w_sh_sm + (uint32_t)((b * WBUF + c * WROW + lane) * 4),
                      wm + (c & 127) * (2 * PD) + (c >> 7) * PD + k0 + lane);
        }
        cp_commit();
    };

    stageB(0, 0);
    for (int tile = 0; tile < NTB; tile++) {
        if (tile + 1 < NTB) { stageB(tile + 1, (tile + 1) & 1); cp_wait<1>(); }
        else                { cp_wait<0>(); }
        __syncthreads();                              // also publishes sisj (tile 0)
        const float* wb = w_sh + (tile & 1) * WBUF;
        const int k0 = tile * KT;
#pragma unroll
        for (int kk = 0; kk < KT; kk++) {
            float w = wb[t * WROW + kk];
#pragma unroll
            for (int r = 0; r < TI; r++)
                accz[r] = fmaf(sisj[r * 256 + which * PD + k0 + kk], w, accz[r]);
        }
        __syncthreads();
    }

    const float bmv = bm[e];
#pragma unroll
    for (int r = 0; r < TI; r++) {
        int i = i0 + r;
        if (which == 0) {
            g_P[i * PD + e] = acc[r];
            g_U[i * PD + e] = accz[r] + bmv;
        } else {
            g_Q[i * PD + e] = acc[r];
            g_V[i * PD + e] = accz[r];
        }
    }
}

// ---------------------------------------------------------------------------
// Kernel 2: z0[i,j,d] = U[i,d] + V[j,d] + P[i,d]*Q[j,d]
// Block = 8 i x 32 j tile; Q/V staged in smem; streaming float4 stores.
// Measured 47.4us @ 64.9% DRAM — near stream floor, unchanged.
// ---------------------------------------------------------------------------
#define BI 8
#define BJ 32

__global__ __launch_bounds__(256) void k2_outer(float* __restrict__ out)
{
    __shared__ float4 q_sh[BJ * 32];   // 16 KB
    __shared__ float4 v_sh[BJ * 32];   // 16 KB

    const int t  = threadIdx.x;
    const int tx = t & 31;             // d quad: d = 4*tx
    const int ty = t >> 5;             // i within tile (0..7)
    const int i  = blockIdx.x * BI + ty;
    const int j0 = blockIdx.y * BJ;

    const float4* __restrict__ P4 = (const float4*)g_P;
    const float4* __restrict__ Q4 = (const float4*)g_Q;
    const float4* __restrict__ U4 = (const float4*)g_U;
    const float4* __restrict__ V4 = (const float4*)g_V;

#pragma unroll
    for (int m = 0; m < (BJ * 32) / 256; m++) {
        int idx = t + m * 256;
        q_sh[idx] = Q4[j0 * 32 + idx];
        v_sh[idx] = V4[j0 * 32 + idx];
    }

    const float4 p = P4[i * 32 + tx];
    const float4 u = U4[i * 32 + tx];
    __syncthreads();

    float4* out4 = (float4*)out;
    size_t base = ((size_t)i * Lq + j0) * 32 + tx;

#pragma unroll 8
    for (int jj = 0; jj < BJ; jj++) {
        float4 q = q_sh[jj * 32 + tx];     // LDS.128, conflict-free
        float4 v = v_sh[jj * 32 + tx];
        float4 o;
        o.x = fmaf(p.x, q.x, u.x + v.x);
        o.y = fmaf(p.y, q.y, u.y + v.y);
        o.z = fmaf(p.z, q.z, u.z + v.z);
        o.w = fmaf(p.w, q.w, u.w + v.w);
        __stcs(&out4[base + (size_t)jj * 32], o);  // streaming store
    }
}

// ---------------------------------------------------------------------------
extern "C" void kernel_launch(void* const* d_in, const int* in_sizes, int n_in,
                              void* d_out, int out_size)
{
    const float* s  = (const float*)d_in[0];
    const float* wi = (const float*)d_in[1];
    const float* bi = (const float*)d_in[2];
    const float* wj = (const float*)d_in[3];
    const float* bj = (const float*)d_in[4];
    const float* wm = (const float*)d_in[5];
    const float* bm = (const float*)d_in[6];
    float* out = (float*)d_out;

    // Idempotent, deterministic, not an allocation: raise dynamic-smem cap.
    cudaFuncSetAttribute(k1_proj, cudaFuncAttributeMaxDynamicSharedMemorySize,
                         K1_SMEM_BYTES);

    k1_proj<<<Lq / TI, 256, K1_SMEM_BYTES>>>(s, wi, bi, wj, bj, wm, bm);

    dim3 grid2(Lq / BI, Lq / BJ);
    k2_outer<<<grid2, 256>>>(out);
}